// round 2
// baseline (speedup 1.0000x reference)
#include <cuda_runtime.h>
#include <math.h>

#define BB 8
#define CC 4
#define HH 96
#define WW 96
#define HW_ (HH*WW)
#define NC 3                   // classes 1..3 (class 0 ignored)
#define NBIN 18051             // squared distances 0..95^2+95^2
#define NPAIR (BB*NC)          // 24
#define SENT 30000             // uint16 sentinel for empty-row distance (> 95^2)

// dynamic smem layout: [2][NBIN] uint32 histograms, then [2][HH][WW] uint16 row dists
#define HIST_WORDS (2*NBIN)
#define ROWD_OFF   (HIST_WORDS*4)
#define SMEM_BYTES (ROWD_OFF + 2*HH*WW*2)   // 181,272 B

__device__ float        g_fr[BB][NC][2];    // percentile results: [b][c-1][0]=fwd, [1]=rev
__device__ unsigned int g_ticket = 0;       // last-block election (wraps -> replay-safe)

// EDT query: min over rows y' of (y-y')^2 + rowdist^2[y'][x], early exit when r^2 >= best.
__device__ __forceinline__ int edt2q(const unsigned short* __restrict__ col, int y) {
    int e = col[y * WW];
#pragma unroll 4
    for (int rr = 1; rr < HH; rr++) {
        int r2 = rr * rr;
        if (r2 >= e) break;
        int up = y - rr, dn = y + rr;
        if (up >= 0) e = min(e, r2 + (int)col[up * WW]);
        if (dn < HH) e = min(e, r2 + (int)col[dn * WW]);
    }
    return e;
}

__global__ void __launch_bounds__(256, 1)
k_all(const float* __restrict__ pred, const int* __restrict__ labels,
      float* __restrict__ out)
{
    extern __shared__ unsigned char smem[];
    unsigned int*   hist = (unsigned int*)smem;                  // [2][NBIN]
    unsigned short* rowd = (unsigned short*)(smem + ROWD_OFF);   // [2][HH][WW]

    __shared__ unsigned int bits[2][HH][3];   // mask bitmaps: [0]=pred(A), [1]=label(B)
    __shared__ unsigned int psum[257];
    __shared__ int s_bin[2];

    int t = threadIdx.x;
    int pair = blockIdx.x;
    int c = pair % NC + 1, b = pair / NC;

    // ---- zero smem histograms ----
    for (int i = t; i < HIST_WORDS; i += 256) hist[i] = 0u;

    // ---- argmax + mask bitmaps (one 32-pixel word per task) ----
    const float* pb = pred + (size_t)b * CC * HW_;
    const int*   lb = labels + (size_t)b * HW_;
    for (int w = t; w < HH * 3; w += 256) {
        int y = w / 3, seg = w - 3 * y;
        int base = y * WW + seg * 32;
        unsigned int wa = 0, wb = 0;
#pragma unroll 8
        for (int k = 0; k < 32; k++) {
            int pix = base + k;
            float v0 = pb[pix];
            float v1 = pb[HW_ + pix];
            float v2 = pb[2 * HW_ + pix];
            float v3 = pb[3 * HW_ + pix];
            float best = v0; int bi = 0;
            if (v1 > best) { best = v1; bi = 1; }     // strict > : first-occurrence argmax
            if (v2 > best) { best = v2; bi = 2; }
            if (v3 > best) { best = v3; bi = 3; }
            if (bi == c)       wa |= 1u << k;
            if (lb[pix] == c)  wb |= 1u << k;
        }
        bits[0][y][seg] = wa;
        bits[1][y][seg] = wb;
    }
    __syncthreads();

    // ---- per-row 1D squared nearest distance (192 serial scans) ----
    for (int task = t; task < 2 * HH; task += 256) {
        int m = task / HH, y = task - HH * (task / HH);
        unsigned int b0 = bits[m][y][0], b1 = bits[m][y][1], b2 = bits[m][y][2];
        unsigned short* o = rowd + m * HH * WW + y * WW;
        int d = 200;
        for (int x = 0; x < WW; x++) {
            unsigned int wv = x < 32 ? b0 : (x < 64 ? b1 : b2);
            d = ((wv >> (x & 31)) & 1u) ? 0 : min(d + 1, 200);
            o[x] = (unsigned short)d;                 // temp: clamped left distance
        }
        d = 200;
        for (int x = WW - 1; x >= 0; x--) {
            unsigned int wv = x < 32 ? b0 : (x < 64 ? b1 : b2);
            d = ((wv >> (x & 31)) & 1u) ? 0 : min(d + 1, 200);
            int dm = min((int)o[x], d);
            o[x] = (dm >= WW) ? (unsigned short)SENT : (unsigned short)(dm * dm);
        }
    }
    __syncthreads();

    // ---- EDT queries over masked pixels -> smem histograms ----
    for (int pix = t; pix < HW_; pix += 256) {
        int y = pix / WW, x = pix - y * WW;
        unsigned int wa = bits[0][y][x >> 5], wb = bits[1][y][x >> 5];
        bool ma = (wa >> (x & 31)) & 1u;
        bool mb = (wb >> (x & 31)) & 1u;
        if (ma) {   // A pixel -> nearest B: EDT of mask B
            int e = edt2q(rowd + HH * WW + x, y);
            atomicAdd(&hist[min(e, NBIN - 1)], 1u);
        }
        if (mb) {   // B pixel -> nearest A: EDT of mask A
            int e = edt2q(rowd + x, y);
            atomicAdd(&hist[NBIN + min(e, NBIN - 1)], 1u);
        }
    }
    __syncthreads();

    // ---- masked percentile (matches jnp fp32 interpolation exactly) ----
    for (int dir = 0; dir < 2; dir++) {
        const unsigned int* h = hist + dir * NBIN;
        const int CH = (NBIN + 255) / 256;
        int s0 = t * CH, s1 = min(s0 + CH, NBIN);
        unsigned int sum = 0;
        for (int i = s0; i < s1; i++) sum += h[i];
        psum[t] = sum;
        __syncthreads();
        if (t == 0) {
            unsigned int acc = 0;
            for (int i = 0; i < 256; i++) { unsigned int v = psum[i]; psum[i] = acc; acc += v; }
            psum[256] = acc;
        }
        __syncthreads();

        unsigned int n = psum[256];
        int nm1 = (int)n - 1; if (nm1 < 0) nm1 = 0;
        float pos = 0.95f * (float)nm1;
        int lo = (int)floorf(pos), hi = (int)ceilf(pos);
        float frac = pos - (float)lo;

        if (n > 0) {
            unsigned int base = psum[t], mend = psum[t + 1];
            if ((unsigned int)lo >= base && (unsigned int)lo < mend) {
                unsigned int acc = base;
                for (int i = s0; i < NBIN; i++) { acc += h[i]; if (acc > (unsigned int)lo) { s_bin[0] = i; break; } }
            }
            if ((unsigned int)hi >= base && (unsigned int)hi < mend) {
                unsigned int acc = base;
                for (int i = s0; i < NBIN; i++) { acc += h[i]; if (acc > (unsigned int)hi) { s_bin[1] = i; break; } }
            }
        }
        __syncthreads();

        if (t == 0) {
            float val;
            if (n == 0) {
                val = __int_as_float(0x7f800000);     // +inf
            } else {
                val = sqrtf((float)s_bin[0]) * (1.0f - frac) + sqrtf((float)s_bin[1]) * frac;
            }
            g_fr[b][c - 1][dir] = val;
        }
        __syncthreads();
    }

    // ---- last-block finalize: batch means + output assembly (18 floats) ----
    if (t == 0) {
        __threadfence();
        unsigned int old = atomicInc(&g_ticket, NPAIR - 1);   // wraps to 0 -> replay-safe
        if (old == NPAIR - 1) {
            __threadfence();
            volatile float* fr = (volatile float*)&g_fr[0][0][0];
            float F[CC], R[CC], M[CC];
            F[0] = R[0] = M[0] = 0.0f;                        // ignored class
            for (int cc = 1; cc < CC; cc++) {
                float sf = 0.f, sr = 0.f, sm = 0.f;
                for (int bb = 0; bb < BB; bb++) {
                    float f = fr[(bb * NC + (cc - 1)) * 2 + 0];
                    float r = fr[(bb * NC + (cc - 1)) * 2 + 1];
                    sf += f; sr += r; sm += fmaxf(f, r);
                }
                F[cc] = sf / (float)BB; R[cc] = sr / (float)BB; M[cc] = sm / (float)BB;
            }
            const float* vs[3] = { M, F, R };                 // output order: MHD, FHD, RHD
            for (int k = 0; k < 3; k++) {
                const float* v = vs[k];
                float s = 0.f, s1v = 0.f;
                for (int cc = 0; cc < CC; cc++) {
                    out[k * 6 + cc] = v[cc];
                    s += v[cc];
                    if (cc >= 1) s1v += v[cc];
                }
                out[k * 6 + 4] = s / (float)CC;
                out[k * 6 + 5] = s1v / (float)(CC - 1);
            }
        }
    }
}

extern "C" void kernel_launch(void* const* d_in, const int* in_sizes, int n_in,
                              void* d_out, int out_size) {
    const float* pred   = (const float*)d_in[0];
    const int*   labels = (const int*)d_in[1];
    float*       out    = (float*)d_out;

    cudaFuncSetAttribute(k_all, cudaFuncAttributeMaxDynamicSharedMemorySize, SMEM_BYTES);
    k_all<<<NPAIR, 256, SMEM_BYTES>>>(pred, labels, out);
}

// round 5
// speedup vs baseline: 2.3058x; 2.3058x over previous
#include <cuda_runtime.h>
#include <math.h>

#define BB 8
#define CC 4
#define HH 96
#define WW 96
#define HW_ (HH*WW)
#define NC 3                   // classes 1..3 (class 0 ignored)
#define NBIN 18051             // squared distances 0..95^2+95^2
#define NPAIR (BB*NC)          // 24
#define NBLK (NPAIR*2)         // 48 blocks: (pair, dir)
#define SENT 30000             // uint16 sentinel for empty-row distance (> 95^2)

// dynamic smem: [NBIN] uint32 histogram, then [HH][WW] uint16 row dists
#define ROWD_OFF (NBIN*4)
#define SMEM_BYTES (ROWD_OFF + HH*WW*2)   // 90,636 B

__device__ float        g_fr[BB][NC][2];  // [b][c-1][0]=fwd, [1]=rev
__device__ unsigned int g_ticket = 0;     // last-block election (wraps -> graph-replay-safe)

// EDT query: min over rows y' of (y-y')^2 + rowdist2[y'][x]; early exit when rr^2 >= best.
__device__ __forceinline__ int edt2q(const unsigned short* __restrict__ col, int y) {
    int e = col[y * WW];
#pragma unroll 4
    for (int rr = 1; rr < HH; rr++) {
        int r2 = rr * rr;
        if (r2 >= e) break;
        int up = y - rr, dn = y + rr;
        if (up >= 0) e = min(e, r2 + (int)col[up * WW]);
        if (dn < HH) e = min(e, r2 + (int)col[dn * WW]);
    }
    return e;
}

__global__ void __launch_bounds__(256, 1)
k_all(const float* __restrict__ pred, const int* __restrict__ labels,
      float* __restrict__ out)
{
    extern __shared__ unsigned char smem[];
    unsigned int*   hist = (unsigned int*)smem;                  // [NBIN]
    unsigned short* rowd = (unsigned short*)(smem + ROWD_OFF);   // [HH][WW] (target mask)

    __shared__ unsigned int bits[2][HH][3];   // [0]=pred mask A, [1]=label mask B
    __shared__ unsigned int psum[257];
    __shared__ int s_bin[2];

    int t = threadIdx.x;
    int bx = blockIdx.x;
    int pair = bx >> 1, dir = bx & 1;         // dir 0: fwd (A->B), dir 1: rev (B->A)
    int c = pair % NC + 1, b = pair / NC;
    int qm = dir;                              // query mask: fwd queries A(0), rev queries B(1)
    int tm = dir ^ 1;                          // target mask (EDT of): fwd->B(1), rev->A(0)

    // ---- zero smem histogram ----
    for (int i = t; i < NBIN; i += 256) hist[i] = 0u;

    // ---- coalesced argmax + ballot bitmap build ----
    const float* pb = pred + (size_t)b * CC * HW_;
    const int*   lb = labels + (size_t)b * HW_;
    for (int pix = t; pix < HW_; pix += 256) {         // HW_ = 36*256 exactly (uniform loop)
        float v0 = pb[pix];
        float v1 = pb[HW_ + pix];
        float v2 = pb[2 * HW_ + pix];
        float v3 = pb[3 * HW_ + pix];
        float best = v0; int bi = 0;
        if (v1 > best) { best = v1; bi = 1; }          // strict > : first-occurrence argmax
        if (v2 > best) { best = v2; bi = 2; }
        if (v3 > best) { best = v3; bi = 3; }
        unsigned int wa = __ballot_sync(0xffffffffu, bi == c);
        unsigned int wb = __ballot_sync(0xffffffffu, lb[pix] == c);
        if ((t & 31) == 0) {                           // warp covers one aligned 32-px word
            int y = pix / WW, seg = (pix - y * WW) >> 5;
            bits[0][y][seg] = wa;
            bits[1][y][seg] = wb;
        }
    }
    __syncthreads();

    // ---- per-row 1D squared nearest distance of TARGET mask (96 serial scans) ----
    for (int y = t; y < HH; y += 256) {
        unsigned int b0 = bits[tm][y][0], b1 = bits[tm][y][1], b2 = bits[tm][y][2];
        unsigned short* o = rowd + y * WW;
        int d = 200;
        for (int x = 0; x < WW; x++) {
            unsigned int wv = x < 32 ? b0 : (x < 64 ? b1 : b2);
            d = ((wv >> (x & 31)) & 1u) ? 0 : min(d + 1, 200);
            o[x] = (unsigned short)d;                  // temp: clamped left distance
        }
        d = 200;
        for (int x = WW - 1; x >= 0; x--) {
            unsigned int wv = x < 32 ? b0 : (x < 64 ? b1 : b2);
            d = ((wv >> (x & 31)) & 1u) ? 0 : min(d + 1, 200);
            int dm = min((int)o[x], d);
            o[x] = (dm >= WW) ? (unsigned short)SENT : (unsigned short)(dm * dm);
        }
    }
    __syncthreads();

    // ---- EDT queries for QUERY-mask pixels -> smem histogram ----
    for (int pix = t; pix < HW_; pix += 256) {
        int y = pix / WW, x = pix - y * WW;
        if ((bits[qm][y][x >> 5] >> (x & 31)) & 1u) {
            int e = edt2q(rowd + x, y);
            atomicAdd(&hist[min(e, NBIN - 1)], 1u);
        }
    }
    __syncthreads();

    // ---- masked percentile (matches jnp fp32 interpolation exactly) ----
    {
        const int CH = (NBIN + 255) / 256;             // 71 bins / thread
        int s0 = t * CH, s1 = min(s0 + CH, NBIN);
        unsigned int sum = 0;
        for (int i = s0; i < s1; i++) sum += hist[i];
        psum[t] = sum;
        __syncthreads();
        if (t == 0) {
            unsigned int acc = 0;
            for (int i = 0; i < 256; i++) { unsigned int v = psum[i]; psum[i] = acc; acc += v; }
            psum[256] = acc;
        }
        __syncthreads();

        unsigned int n = psum[256];
        int nm1 = (int)n - 1; if (nm1 < 0) nm1 = 0;
        float pos = 0.95f * (float)nm1;
        int lo = (int)floorf(pos), hi = (int)ceilf(pos);
        float frac = pos - (float)lo;

        if (n > 0) {
            unsigned int base = psum[t], mend = psum[t + 1];
            if ((unsigned int)lo >= base && (unsigned int)lo < mend) {
                unsigned int acc = base;
                for (int i = s0; i < NBIN; i++) { acc += hist[i]; if (acc > (unsigned int)lo) { s_bin[0] = i; break; } }
            }
            if ((unsigned int)hi >= base && (unsigned int)hi < mend) {
                unsigned int acc = base;
                for (int i = s0; i < NBIN; i++) { acc += hist[i]; if (acc > (unsigned int)hi) { s_bin[1] = i; break; } }
            }
        }
        __syncthreads();

        if (t == 0) {
            float val;
            if (n == 0) {
                val = __int_as_float(0x7f800000);      // +inf
            } else {
                val = sqrtf((float)s_bin[0]) * (1.0f - frac) + sqrtf((float)s_bin[1]) * frac;
            }
            g_fr[b][c - 1][dir] = val;
        }
    }

    // ---- last-block finalize: batch means + output (18 floats) ----
    if (t == 0) {
        __threadfence();
        unsigned int old = atomicInc(&g_ticket, NBLK - 1);   // wraps to 0 -> replay-safe
        if (old == NBLK - 1) {
            __threadfence();
            volatile float* fr = (volatile float*)&g_fr[0][0][0];
            float F[CC], R[CC], M[CC];
            F[0] = R[0] = M[0] = 0.0f;                       // ignored class
            for (int cc = 1; cc < CC; cc++) {
                float sf = 0.f, sr = 0.f, sm = 0.f;
                for (int bb = 0; bb < BB; bb++) {
                    float f = fr[(bb * NC + (cc - 1)) * 2 + 0];
                    float r = fr[(bb * NC + (cc - 1)) * 2 + 1];
                    sf += f; sr += r; sm += fmaxf(f, r);
                }
                F[cc] = sf / (float)BB; R[cc] = sr / (float)BB; M[cc] = sm / (float)BB;
            }
            const float* vs[3] = { M, F, R };                // output order: MHD, FHD, RHD
            for (int k = 0; k < 3; k++) {
                const float* v = vs[k];
                float s = 0.f, s1v = 0.f;
                for (int cc = 0; cc < CC; cc++) {
                    out[k * 6 + cc] = v[cc];
                    s += v[cc];
                    if (cc >= 1) s1v += v[cc];
                }
                out[k * 6 + 4] = s / (float)CC;
                out[k * 6 + 5] = s1v / (float)(CC - 1);
            }
        }
    }
}

extern "C" void kernel_launch(void* const* d_in, const int* in_sizes, int n_in,
                              void* d_out, int out_size) {
    const float* pred   = (const float*)d_in[0];
    const int*   labels = (const int*)d_in[1];
    float*       out    = (float*)d_out;

    (void)cudaFuncSetAttribute(k_all, cudaFuncAttributeMaxDynamicSharedMemorySize, SMEM_BYTES);
    k_all<<<NBLK, 256, SMEM_BYTES>>>(pred, labels, out);
}

// round 6
// speedup vs baseline: 3.6283x; 1.5736x over previous
#include <cuda_runtime.h>
#include <math.h>

#define BB 8
#define CC 4
#define HH 96
#define WW 96
#define HW_ (HH*WW)
#define NC 3                   // classes 1..3 (class 0 ignored)
#define NBIN 18051             // squared distances 0..95^2+95^2
#define NPAIR (BB*NC)          // 24
#define NBLK (NPAIR*2)         // 48 blocks: (pair, dir)
#define NT 1024                // threads per block
#define SENT 30000             // uint16 sentinel: empty row (> 95^2)

// dynamic smem: [NBIN] uint32 histogram, then [HH][WW] uint16 row dists
#define ROWD_OFF (NBIN*4)
#define SMEM_BYTES (ROWD_OFF + HH*WW*2)   // 90,636 B

__device__ float        g_fr[BB][NC][2];  // [b][c-1][0]=fwd, [1]=rev
__device__ unsigned int g_ticket = 0;     // last-block election (wraps -> graph-replay-safe)

// EDT query: min over rows y' of (y-y')^2 + rowdist2[y'][x]; early exit when rr^2 >= best.
__device__ __forceinline__ int edt2q(const unsigned short* __restrict__ col, int y) {
    int e = col[y * WW];
#pragma unroll 4
    for (int rr = 1; rr < HH; rr++) {
        int r2 = rr * rr;
        if (r2 >= e) break;
        int up = y - rr, dn = y + rr;
        if (up >= 0) e = min(e, r2 + (int)col[up * WW]);
        if (dn < HH) e = min(e, r2 + (int)col[dn * WW]);
    }
    return e;
}

// nearest set bit <= x in 96-bit mask (words b0..b2); very-negative if none
__device__ __forceinline__ int nearest_left(unsigned b0, unsigned b1, unsigned b2, int x) {
    int j = x >> 5, o = x & 31;
    unsigned w[3] = { b0, b1, b2 };
    unsigned m = w[j] & (0xFFFFFFFFu >> (31 - o));
    if (m) return (j << 5) + 31 - __clz(m);
#pragma unroll
    for (int k = 1; k >= 0; k--)
        if (k < j && w[k]) return (k << 5) + 31 - __clz(w[k]);
    return -1000;
}
// nearest set bit >= x; very-positive if none
__device__ __forceinline__ int nearest_right(unsigned b0, unsigned b1, unsigned b2, int x) {
    int j = x >> 5, o = x & 31;
    unsigned w[3] = { b0, b1, b2 };
    unsigned m = w[j] & (0xFFFFFFFFu << o);
    if (m) return (j << 5) + __ffs(m) - 1;
#pragma unroll
    for (int k = 1; k < 3; k++)
        if (k > j && w[k]) return (k << 5) + __ffs(w[k]) - 1;
    return 1000;
}

__global__ void __launch_bounds__(NT, 1)
k_all(const float* __restrict__ pred, const int* __restrict__ labels,
      float* __restrict__ out)
{
    extern __shared__ unsigned char smem[];
    unsigned int*   hist = (unsigned int*)smem;                  // [NBIN]
    unsigned short* rowd = (unsigned short*)(smem + ROWD_OFF);   // [HH][WW] (target mask)

    __shared__ unsigned int bits[2][HH][3];   // [0]=pred mask A, [1]=label mask B
    __shared__ unsigned int warp_scan[32];    // warp totals / prefixes
    __shared__ unsigned int s_total;
    __shared__ int s_bin[2];

    int t = threadIdx.x;
    int lane = t & 31, wid = t >> 5;
    int bx = blockIdx.x;
    int pair = bx >> 1, dir = bx & 1;         // dir 0: fwd (A->B), dir 1: rev (B->A)
    int c = pair % NC + 1, b = pair / NC;
    int qm = dir;                              // query mask: fwd->A(0), rev->B(1)
    int tm = dir ^ 1;                          // target (EDT of): fwd->B(1), rev->A(0)

    // ---- zero smem histogram (18 iters) ----
    for (int i = t; i < NBIN; i += NT) hist[i] = 0u;

    // ---- coalesced argmax + ballot bitmap build (9 iters) ----
    const float* pb = pred + (size_t)b * CC * HW_;
    const int*   lb = labels + (size_t)b * HW_;
#pragma unroll 3
    for (int pix = t; pix < HW_; pix += NT) {          // HW_ = 9*1024 exactly
        float v0 = pb[pix];
        float v1 = pb[HW_ + pix];
        float v2 = pb[2 * HW_ + pix];
        float v3 = pb[3 * HW_ + pix];
        int li = lb[pix];
        float best = v0; int bi = 0;
        if (v1 > best) { best = v1; bi = 1; }          // strict > : first-occurrence argmax
        if (v2 > best) { best = v2; bi = 2; }
        if (v3 > best) { best = v3; bi = 3; }
        unsigned int wa = __ballot_sync(0xffffffffu, bi == c);
        unsigned int wb = __ballot_sync(0xffffffffu, li == c);
        if (lane == 0) {                               // warp covers one aligned 32-px word
            int y = pix / WW, seg = (pix - y * WW) >> 5;
            bits[0][y][seg] = wa;
            bits[1][y][seg] = wb;
        }
    }
    __syncthreads();

    // ---- per-pixel 1D row distance of TARGET mask via bit tricks (9 iters) ----
    for (int pix = t; pix < HW_; pix += NT) {
        int y = pix / WW, x = pix - y * WW;
        unsigned b0 = bits[tm][y][0], b1 = bits[tm][y][1], b2 = bits[tm][y][2];
        int l = nearest_left(b0, b1, b2, x);
        int r = nearest_right(b0, b1, b2, x);
        int d = min(x - l, r - x);
        rowd[pix] = (d > 95) ? (unsigned short)SENT : (unsigned short)(d * d);
    }
    __syncthreads();

    // ---- EDT queries for QUERY-mask pixels -> smem histogram (9 iters) ----
    for (int pix = t; pix < HW_; pix += NT) {
        int y = pix / WW, x = pix - y * WW;
        if ((bits[qm][y][x >> 5] >> (x & 31)) & 1u) {
            int e = edt2q(rowd + x, y);
            atomicAdd(&hist[min(e, NBIN - 1)], 1u);
        }
    }
    __syncthreads();

    // ---- masked percentile (matches jnp fp32 interpolation exactly) ----
    {
        const int CH = (NBIN + NT - 1) / NT;           // 18 bins / thread
        int s0 = t * CH, s1 = min(s0 + CH, NBIN);
        unsigned int own = 0;
        for (int i = s0; i < s1; i++) own += hist[i];

        // hierarchical exclusive block scan (shfl warp scan + warp-0 scan of totals)
        unsigned int inc = own;
#pragma unroll
        for (int o = 1; o < 32; o <<= 1) {
            unsigned int v = __shfl_up_sync(0xffffffffu, inc, o);
            if (lane >= o) inc += v;
        }
        if (lane == 31) warp_scan[wid] = inc;          // warp total
        __syncthreads();
        if (wid == 0) {
            unsigned int wv = warp_scan[lane];
            unsigned int wi = wv;
#pragma unroll
            for (int o = 1; o < 32; o <<= 1) {
                unsigned int v = __shfl_up_sync(0xffffffffu, wi, o);
                if (lane >= o) wi += v;
            }
            warp_scan[lane] = wi - wv;                 // exclusive warp prefix
            if (lane == 31) s_total = wi;
        }
        __syncthreads();
        unsigned int base = warp_scan[wid] + (inc - own);  // exclusive prefix for this thread
        unsigned int mend = base + own;
        unsigned int n = s_total;

        int nm1 = (int)n - 1; if (nm1 < 0) nm1 = 0;
        float pos = 0.95f * (float)nm1;
        int lo = (int)floorf(pos), hi = (int)ceilf(pos);
        float frac = pos - (float)lo;

        if (n > 0) {
            if ((unsigned int)lo >= base && (unsigned int)lo < mend) {
                unsigned int acc = base;
                for (int i = s0; i < NBIN; i++) { acc += hist[i]; if (acc > (unsigned int)lo) { s_bin[0] = i; break; } }
            }
            if ((unsigned int)hi >= base && (unsigned int)hi < mend) {
                unsigned int acc = base;
                for (int i = s0; i < NBIN; i++) { acc += hist[i]; if (acc > (unsigned int)hi) { s_bin[1] = i; break; } }
            }
        }
        __syncthreads();

        if (t == 0) {
            float val;
            if (n == 0) {
                val = __int_as_float(0x7f800000);      // +inf
            } else {
                val = sqrtf((float)s_bin[0]) * (1.0f - frac) + sqrtf((float)s_bin[1]) * frac;
            }
            g_fr[b][c - 1][dir] = val;
        }
    }

    // ---- last-block finalize: batch means + output (18 floats) ----
    if (t == 0) {
        __threadfence();
        unsigned int old = atomicInc(&g_ticket, NBLK - 1);   // wraps to 0 -> replay-safe
        if (old == NBLK - 1) {
            __threadfence();
            volatile float* fr = (volatile float*)&g_fr[0][0][0];
            float F[CC], R[CC], M[CC];
            F[0] = R[0] = M[0] = 0.0f;                       // ignored class
            for (int cc = 1; cc < CC; cc++) {
                float sf = 0.f, sr = 0.f, sm = 0.f;
                for (int bb = 0; bb < BB; bb++) {
                    float f = fr[(bb * NC + (cc - 1)) * 2 + 0];
                    float r = fr[(bb * NC + (cc - 1)) * 2 + 1];
                    sf += f; sr += r; sm += fmaxf(f, r);
                }
                F[cc] = sf / (float)BB; R[cc] = sr / (float)BB; M[cc] = sm / (float)BB;
            }
            const float* vs[3] = { M, F, R };                // output order: MHD, FHD, RHD
            for (int k = 0; k < 3; k++) {
                const float* v = vs[k];
                float s = 0.f, s1v = 0.f;
                for (int cc = 0; cc < CC; cc++) {
                    out[k * 6 + cc] = v[cc];
                    s += v[cc];
                    if (cc >= 1) s1v += v[cc];
                }
                out[k * 6 + 4] = s / (float)CC;
                out[k * 6 + 5] = s1v / (float)(CC - 1);
            }
        }
    }
}

extern "C" void kernel_launch(void* const* d_in, const int* in_sizes, int n_in,
                              void* d_out, int out_size) {
    const float* pred   = (const float*)d_in[0];
    const int*   labels = (const int*)d_in[1];
    float*       out    = (float*)d_out;

    (void)cudaFuncSetAttribute(k_all, cudaFuncAttributeMaxDynamicSharedMemorySize, SMEM_BYTES);
    k_all<<<NBLK, NT, SMEM_BYTES>>>(pred, labels, out);
}